// round 5
// baseline (speedup 1.0000x reference)
#include <cuda_runtime.h>
#include <math.h>

// Problem constants (fixed shapes): B=4096, NSPIN=2, NPS=16, D=256, NION=8, DIM=3
#define BMAX 4096

// Scratch (static device globals -- no allocation)
__device__ float g_M[BMAX * 32 * 16];   // M[b][sn][o] fp32
__device__ float g_G[2 * 8 * 16 * 8];   // per (s,i,o): {gxx,gyy,gzz,2gxy,2gxz,2gyz,ion,pad}

// ---------------------------------------------------------------------------
// Kernel 0: precompute G = A^T A (A = env_dim[s,i,o], 3x3) and carry env_ion.
// 256 entries total.
// ---------------------------------------------------------------------------
__global__ void precompute_G_kernel(const float* __restrict__ ED,
                                    const float* __restrict__ EI) {
    int t = threadIdx.x;              // t = (s*8+i)*16+o, 0..255
    const float* A = ED + t * 9;      // A[e][d], row-major 3x3
    float a00=A[0],a01=A[1],a02=A[2];
    float a10=A[3],a11=A[4],a12=A[5];
    float a20=A[6],a21=A[7],a22=A[8];
    float gxx = a00*a00 + a10*a10 + a20*a20;
    float gyy = a01*a01 + a11*a11 + a21*a21;
    float gzz = a02*a02 + a12*a12 + a22*a22;
    float gxy = a00*a01 + a10*a11 + a20*a21;
    float gxz = a00*a02 + a10*a12 + a20*a22;
    float gyz = a01*a02 + a11*a12 + a21*a22;
    float* gp = g_G + t * 8;
    gp[0] = gxx; gp[1] = gyy; gp[2] = gzz;
    gp[3] = 2.0f*gxy; gp[4] = 2.0f*gxz; gp[5] = 2.0f*gyz;
    gp[6] = EI[t]; gp[7] = 0.0f;
}

// ---------------------------------------------------------------------------
// Kernel 1: fused  y = x@W + b  and  env = sum_i exp(-sqrt(r^T G r)) * ion,
// writes M = y*env to g_M.
// CTA = 8 batches (256 rows of 256-dim x). 256 threads, each thread computes a
// 4-row x 4-col output tile. smem-tiled GEMM over K=256 in chunks of 32.
// ---------------------------------------------------------------------------
__global__ __launch_bounds__(256) void main_kernel(
    const float* __restrict__ X,      // [B][32][256]
    const float* __restrict__ R,      // [B][32][8][3]
    const float* __restrict__ W,      // [2][256][16]
    const float* __restrict__ Bias)   // [2][16]
{
    __shared__ float  sx[256][33];     // x tile [row][dlocal], stride 33 (bank-safe)
    __shared__ float4 sw4[2][32][4];   // W tile [s][dlocal][o/4]
    __shared__ float4 sG4[256][2];     // G table [(s*8+i)*16+o][2]

    const int tid  = threadIdx.x;
    const int blk  = blockIdx.x;
    const int rg   = tid >> 2;         // rowgroup 0..63
    const int cg   = tid & 3;          // colgroup 0..3
    const int row0 = rg << 2;          // first of 4 rows (same batch, same spin)
    const int s    = (row0 & 31) >> 4; // spin of this thread's rows

    // Stage G table into smem (read after first chunk's __syncthreads)
    {
        const float4* gg = (const float4*)g_G;
        sG4[tid][0] = gg[tid * 2];
        sG4[tid][1] = gg[tid * 2 + 1];
    }

    float bb[4];
#pragma unroll
    for (int j = 0; j < 4; j++) bb[j] = Bias[s * 16 + (cg << 2) + j];

    float acc[4][4];
#pragma unroll
    for (int i = 0; i < 4; i++)
#pragma unroll
        for (int j = 0; j < 4; j++) acc[i][j] = 0.0f;

    const float* Xblk = X + (size_t)blk * 256 * 256;

    for (int ch = 0; ch < 8; ch++) {
        __syncthreads();
        const int d0 = ch * 32;
        // Load x tile: 2048 float4s, coalesced; conflict-free scattered stores.
#pragma unroll
        for (int it = 0; it < 8; it++) {
            int f4 = it * 256 + tid;
            int r  = f4 >> 3;
            int dq = f4 & 7;
            float4 v = *(const float4*)(Xblk + (size_t)r * 256 + d0 + dq * 4);
            float* dst = &sx[r][dq * 4];
            dst[0] = v.x; dst[1] = v.y; dst[2] = v.z; dst[3] = v.w;
        }
        // Load W tile: 256 float4s (both spins)
        {
            int s_  = tid >> 7;
            int rem = tid & 127;
            int d   = rem >> 2;
            int oq  = rem & 3;
            sw4[s_][d][oq] = *(const float4*)(W + s_ * 4096 + (d0 + d) * 16 + oq * 4);
        }
        __syncthreads();
#pragma unroll
        for (int d = 0; d < 32; d++) {
            float4 wv = sw4[s][d][cg];
            float x0 = sx[row0 + 0][d];
            float x1 = sx[row0 + 1][d];
            float x2 = sx[row0 + 2][d];
            float x3 = sx[row0 + 3][d];
            acc[0][0] += x0 * wv.x; acc[0][1] += x0 * wv.y; acc[0][2] += x0 * wv.z; acc[0][3] += x0 * wv.w;
            acc[1][0] += x1 * wv.x; acc[1][1] += x1 * wv.y; acc[1][2] += x1 * wv.z; acc[1][3] += x1 * wv.w;
            acc[2][0] += x2 * wv.x; acc[2][1] += x2 * wv.y; acc[2][2] += x2 * wv.z; acc[2][3] += x2 * wv.w;
            acc[3][0] += x3 * wv.x; acc[3][1] += x3 * wv.y; acc[3][2] += x3 * wv.z; acc[3][3] += x3 * wv.w;
        }
    }

    // Envelope + M assembly + store
#pragma unroll
    for (int ri = 0; ri < 4; ri++) {
        const int grow = blk * 256 + row0 + ri;     // = b*32 + sn
        const float4* rp = (const float4*)(R + (size_t)grow * 24);
        float rv[24];
#pragma unroll
        for (int q = 0; q < 6; q++) {
            float4 t = rp[q];
            rv[q*4+0] = t.x; rv[q*4+1] = t.y; rv[q*4+2] = t.z; rv[q*4+3] = t.w;
        }
        float env[4] = {0.0f, 0.0f, 0.0f, 0.0f};
#pragma unroll
        for (int i = 0; i < 8; i++) {
            float px = rv[i*3 + 0];
            float py = rv[i*3 + 1];
            float pz = rv[i*3 + 2];
#pragma unroll
            for (int cj = 0; cj < 4; cj++) {
                int gi = s * 128 + i * 16 + (cg << 2) + cj;
                float4 ga = sG4[gi][0];   // gxx,gyy,gzz,2gxy
                float4 gb = sG4[gi][1];   // 2gxz,2gyz,ion,pad
                float q1 = px * (ga.x * px + ga.w * py + gb.x * pz)
                         + py * (ga.y * py + gb.y * pz)
                         + pz * (ga.z * pz);
                float rl;
                asm("sqrt.approx.f32 %0, %1;" : "=f"(rl) : "f"(q1));
                env[cj] += __expf(-rl) * gb.z;
            }
        }
        float4 mo;
        mo.x = (acc[ri][0] + bb[0]) * env[0];
        mo.y = (acc[ri][1] + bb[1]) * env[1];
        mo.z = (acc[ri][2] + bb[2]) * env[2];
        mo.w = (acc[ri][3] + bb[3]) * env[3];
        *(float4*)&g_M[(size_t)grow * 16 + (cg << 2)] = mo;
    }
}

// ---------------------------------------------------------------------------
// Kernel 2: per (b,s) 16x16 matrix M, compute
//   cof_i = M[i,0] * det(M) * (M^{-1})_{0,i}
// via fp64 Gauss-Jordan on A = M^T with virtual partial pivoting.
// One matrix per 16-lane half-warp (width-16 shuffles); 2 matrices / warp.
// ---------------------------------------------------------------------------
__global__ __launch_bounds__(256) void cof_kernel(float* __restrict__ out, int npair) {
    const unsigned FULL = 0xffffffffu;
    int gtid = blockIdx.x * blockDim.x + threadIdx.x;
    int mat  = gtid >> 4;          // (b,s) pair index
    int r    = gtid & 15;          // row of A (= column of M)
    if (mat >= npair) return;

    const float* Mp = g_M + (size_t)mat * 256;  // M row-major [n][o]
    double a[16];
#pragma unroll
    for (int c = 0; c < 16; c++) a[c] = (double)Mp[c * 16 + r];  // A[r][c] = M[c][r]
    double rhs = (r == 0) ? 1.0 : 0.0;
    double mi0 = (double)Mp[r * 16];            // M[r][0]

    double det = 1.0;
    int  sstep = 16;     // step at which this lane was pivot
    int  myp   = 0;      // pivot lane chosen at step k == r
    bool elim  = false;

#pragma unroll
    for (int k = 0; k < 16; k++) {
        // --- pivot selection: argmax |a[k]| among non-eliminated lanes ---
        double cand = elim ? -1.0 : fabs(a[k]);
        int bl = r;
#pragma unroll
        for (int off = 8; off > 0; off >>= 1) {
            double ov = __shfl_xor_sync(FULL, cand, off, 16);
            int    ol = __shfl_xor_sync(FULL, bl,   off, 16);
            if (ov > cand || (ov == cand && ol < bl)) { cand = ov; bl = ol; }
        }
        int p = bl;
        if (k == r) myp = p;

        double pv = __shfl_sync(FULL, a[k], p, 16);
        det *= pv;

        // Pivot lane normalizes its trailing row + rhs
        if (r == p) {
            double inv = 1.0 / pv;
#pragma unroll
            for (int c = k + 1; c < 16; c++) a[c] *= inv;
            rhs *= inv;
            elim  = true;
            sstep = k;
        }
        // Eliminate column k from all other rows (Gauss-Jordan)
        double f = a[k];
#pragma unroll
        for (int c = k + 1; c < 16; c++) {
            double pc = __shfl_sync(FULL, a[c], p, 16);
            if (r != p) a[c] -= f * pc;
        }
        double prh = __shfl_sync(FULL, rhs, p, 16);
        if (r != p) rhs -= f * prh;
    }

    // Permutation parity via inversion count of sstep sequence
    int invc = 0;
#pragma unroll
    for (int j = 0; j < 16; j++) {
        int sj = __shfl_sync(FULL, sstep, j, 16);
        if (j > r && sj < sstep) invc++;
    }
#pragma unroll
    for (int off = 8; off > 0; off >>= 1) invc += __shfl_xor_sync(FULL, invc, off, 16);
    if (invc & 1) det = -det;

    // z_i sits at the lane that pivoted at step i
    double z = __shfl_sync(FULL, rhs, myp, 16);

    out[(size_t)mat * 16 + r] = (float)(mi0 * det * z);
}

// ---------------------------------------------------------------------------
extern "C" void kernel_launch(void* const* d_in, const int* in_sizes, int n_in,
                              void* d_out, int out_size) {
    const float* X    = (const float*)d_in[0];   // eq_inputs [B][32][256]
    const float* R    = (const float*)d_in[1];   // r_ei      [B][32][8][3]
    const float* W    = (const float*)d_in[2];   // W         [2][256][16]
    const float* Bias = (const float*)d_in[3];   // b         [2][16]
    const float* ED   = (const float*)d_in[4];   // env_dim   [2][8][16][3][3]
    const float* EI   = (const float*)d_in[5];   // env_ion   [2][8][16]
    float* out = (float*)d_out;

    int B = in_sizes[0] / (32 * 256);            // 4096
    if (B > BMAX) B = BMAX;

    precompute_G_kernel<<<1, 256>>>(ED, EI);
    main_kernel<<<B / 8, 256>>>(X, R, W, Bias);
    int npair = B * 2;
    cof_kernel<<<npair / 16, 256>>>(out, npair);
    (void)n_in; (void)out_size;
}

// round 6
// speedup vs baseline: 1.2114x; 1.2114x over previous
#include <cuda_runtime.h>
#include <math.h>

// Fixed shapes: B=4096, NSPIN=2, NPS=16, D=256, NION=8, DIM=3
#define BMAX 4096
typedef unsigned long long ull;

// Scratch (static device global -- no allocation)
__device__ float g_M[BMAX * 32 * 16];   // M[b][sn][o] fp32

// ---------------- f32x2 helpers (packed dual-FMA, sm_100+) ----------------
__device__ __forceinline__ ull fsplat(float a) {
    ull r; asm("mov.b64 %0, {%1, %1};" : "=l"(r) : "f"(a)); return r;
}
__device__ __forceinline__ ull fma2(ull a, ull b, ull c) {
    ull d; asm("fma.rn.f32x2 %0, %1, %2, %3;" : "=l"(d) : "l"(a), "l"(b), "l"(c)); return d;
}
__device__ __forceinline__ float pklo(ull v) { return __uint_as_float((unsigned)v); }
__device__ __forceinline__ float pkhi(ull v) { return __uint_as_float((unsigned)(v >> 32)); }

#define CP16(dst, src) \
    asm volatile("cp.async.cg.shared.global [%0], [%1], 16;" :: "r"(dst), "l"(src))

// Dynamic smem layout (floats):
//   sX: [2][256 rows][32]  XOR-swizzled  -> 16384 floats (65536 B)
//   sW: [2][256][16]                      ->  8192 floats (32768 B)
//   sG: [256][8]                          ->  2048 floats ( 8192 B)
#define SMEM_FLOATS (16384 + 8192 + 2048)
#define SMEM_BYTES  (SMEM_FLOATS * 4)     // 106496

// ---------------------------------------------------------------------------
// Kernel 1: fused  y = x@W + b  and  env = sum_i exp(-sqrt(r^T G r)) * ion,
// writes M = y*env to g_M.  CTA = 8 batches (256 rows). 256 threads, each
// computes 4 rows x 4 cols.  cp.async double-buffered K-chunks (32) with
// fma.rn.f32x2 inner product (column-paired accumulators).
// G = A^T A computed in-CTA (replaces separate precompute kernel).
// ---------------------------------------------------------------------------
__global__ __launch_bounds__(256, 2) void main_kernel(
    const float* __restrict__ X,      // [B][32][256]
    const float* __restrict__ R,      // [B][32][8][3]
    const float* __restrict__ W,      // [2][256][16]
    const float* __restrict__ Bias,   // [2][16]
    const float* __restrict__ ED,     // [2][8][16][3][3]
    const float* __restrict__ EI)     // [2][8][16]
{
    extern __shared__ float smem[];
    float* sX = smem;             // swizzled X tiles
    float* sW = smem + 16384;     // full W
    float* sG = smem + 24576;     // G table

    const int tid  = threadIdx.x;
    const int blk  = blockIdx.x;
    const int rg   = tid >> 2;
    const int cg   = tid & 3;
    const int row0 = rg << 2;           // 4 rows, same spin
    const int s    = (row0 >> 4) & 1;

    const unsigned sXaddr = (unsigned)__cvta_generic_to_shared(sX);
    const unsigned sWaddr = (unsigned)__cvta_generic_to_shared(sW);

    const float* Xblk = X + (size_t)blk * 65536;

    // --- prologue: async-copy full W (8192 floats) + X chunk 0 ---
#pragma unroll
    for (int it = 0; it < 8; it++) {
        int c = it * 256 + tid;                       // 2048 16B chunks
        CP16(sWaddr + c * 16, W + c * 4);
    }
#pragma unroll
    for (int it = 0; it < 8; it++) {
        int idx = it * 256 + tid;
        int r = idx >> 3, dq = idx & 7;
        CP16(sXaddr + (r << 7) + ((dq ^ (r & 7)) << 4), Xblk + r * 256 + dq * 4);
    }
    asm volatile("cp.async.commit_group;");

    // --- G = A^T A per (s,i,o), one entry per thread (overlaps cp.async) ---
    {
        const float* A = ED + tid * 9;
        float a00=A[0],a01=A[1],a02=A[2];
        float a10=A[3],a11=A[4],a12=A[5];
        float a20=A[6],a21=A[7],a22=A[8];
        float* gp = sG + tid * 8;
        gp[0] = a00*a00 + a10*a10 + a20*a20;
        gp[1] = a01*a01 + a11*a11 + a21*a21;
        gp[2] = a02*a02 + a12*a12 + a22*a22;
        gp[3] = 2.0f*(a00*a01 + a10*a11 + a20*a21);
        gp[4] = 2.0f*(a00*a02 + a10*a12 + a20*a22);
        gp[5] = 2.0f*(a01*a02 + a11*a12 + a21*a22);
        gp[6] = EI[tid];
        gp[7] = 0.0f;
    }

    float bb[4];
#pragma unroll
    for (int j = 0; j < 4; j++) bb[j] = Bias[s * 16 + (cg << 2) + j];

    // accp[i][p]: packed (col 4cg+2p, col 4cg+2p+1) accumulators for row0+i
    ull accp[4][2];
#pragma unroll
    for (int i = 0; i < 4; i++) { accp[i][0] = 0ull; accp[i][1] = 0ull; }

#pragma unroll 1
    for (int ch = 0; ch < 8; ch++) {
        if (ch < 7) {
            const float* src   = Xblk + (ch + 1) * 32;
            unsigned     dbase = sXaddr + ((unsigned)((ch + 1) & 1)) * 32768u;
#pragma unroll
            for (int it = 0; it < 8; it++) {
                int idx = it * 256 + tid;
                int r = idx >> 3, dq = idx & 7;
                CP16(dbase + (r << 7) + ((dq ^ (r & 7)) << 4), src + r * 256 + dq * 4);
            }
            asm volatile("cp.async.commit_group;");
            asm volatile("cp.async.wait_group 1;");
        } else {
            asm volatile("cp.async.wait_group 0;");
        }
        __syncthreads();

        const float* xb = sX + (ch & 1) * 8192;
        const float* wb = sW + s * 4096 + ch * 512;   // chunk: d0 = ch*32
#pragma unroll
        for (int d4 = 0; d4 < 8; d4++) {
            float4 xq[4];
#pragma unroll
            for (int i = 0; i < 4; i++) {
                int r = row0 + i;
                xq[i] = *(const float4*)(xb + (r << 5) + ((d4 ^ (r & 7)) << 2));
            }
#pragma unroll
            for (int dd = 0; dd < 4; dd++) {
                const float* wp = wb + (d4 * 4 + dd) * 16 + (cg << 2);
                ull w01 = *(const ull*)wp;        // (w_j, w_{j+1}) contiguous pair
                ull w23 = *(const ull*)(wp + 2);
#pragma unroll
                for (int i = 0; i < 4; i++) {
                    float xv = (dd == 0) ? xq[i].x : (dd == 1) ? xq[i].y
                             : (dd == 2) ? xq[i].z : xq[i].w;
                    ull xs = fsplat(xv);
                    accp[i][0] = fma2(xs, w01, accp[i][0]);
                    accp[i][1] = fma2(xs, w23, accp[i][1]);
                }
            }
        }
        __syncthreads();
    }

    // --- Envelope + M assembly + store ---
#pragma unroll
    for (int ri = 0; ri < 4; ri++) {
        const int grow = blk * 256 + row0 + ri;     // = b*32 + sn
        const float4* rp = (const float4*)(R + (size_t)grow * 24);
        float rv[24];
#pragma unroll
        for (int q = 0; q < 6; q++) {
            float4 t = rp[q];
            rv[q*4+0] = t.x; rv[q*4+1] = t.y; rv[q*4+2] = t.z; rv[q*4+3] = t.w;
        }
        float env[4] = {0.0f, 0.0f, 0.0f, 0.0f};
#pragma unroll
        for (int i = 0; i < 8; i++) {
            float px = rv[i*3 + 0];
            float py = rv[i*3 + 1];
            float pz = rv[i*3 + 2];
#pragma unroll
            for (int cj = 0; cj < 4; cj++) {
                int gi = s * 128 + i * 16 + (cg << 2) + cj;
                float4 ga = *(const float4*)(sG + gi * 8);      // gxx,gyy,gzz,2gxy
                float4 gb = *(const float4*)(sG + gi * 8 + 4);  // 2gxz,2gyz,ion,pad
                float q1 = px * (ga.x * px + ga.w * py + gb.x * pz)
                         + py * (ga.y * py + gb.y * pz)
                         + pz * (ga.z * pz);
                float rl;
                asm("sqrt.approx.f32 %0, %1;" : "=f"(rl) : "f"(q1));
                env[cj] += __expf(-rl) * gb.z;
            }
        }
        float4 mo;
        mo.x = (pklo(accp[ri][0]) + bb[0]) * env[0];
        mo.y = (pkhi(accp[ri][0]) + bb[1]) * env[1];
        mo.z = (pklo(accp[ri][1]) + bb[2]) * env[2];
        mo.w = (pkhi(accp[ri][1]) + bb[3]) * env[3];
        *(float4*)&g_M[(size_t)grow * 16 + (cg << 2)] = mo;
    }
}

// ---------------------------------------------------------------------------
// Kernel 2: per (b,s) 16x16 matrix M, cof_i = M[i,0] * det(M) * (M^{-1})_{0,i}
// fp64 Gauss-Jordan on A = M^T, virtual partial pivoting. One matrix per
// 16-lane half-warp. Pivot argmax via single redux.sync on packed fp32 key.
// ---------------------------------------------------------------------------
__global__ __launch_bounds__(256) void cof_kernel(float* __restrict__ out, int npair) {
    const unsigned FULL = 0xffffffffu;
    int gtid = blockIdx.x * blockDim.x + threadIdx.x;
    int mat  = gtid >> 4;          // (b,s) pair index
    int r    = gtid & 15;          // row of A (= column of M)
    if (mat >= npair) return;

    const unsigned hmask = 0xFFFFu << (threadIdx.x & 16);  // this half-warp's lanes

    const float* Mp = g_M + (size_t)mat * 256;  // M row-major [n][o]
    double a[16];
#pragma unroll
    for (int c = 0; c < 16; c++) a[c] = (double)Mp[c * 16 + r];  // A[r][c] = M[c][r]
    double rhs = (r == 0) ? 1.0 : 0.0;
    double mi0 = (double)Mp[r * 16];            // M[r][0]

    double det = 1.0;
    int  sstep = 16;     // step at which this lane was pivot
    int  myp   = 0;      // pivot lane chosen at step k == r
    bool elim  = false;

#pragma unroll
    for (int k = 0; k < 16; k++) {
        // --- pivot: argmax |a[k]| among non-eliminated lanes (1 redux) ---
        unsigned key = 0u;
        if (!elim) {
            unsigned mb = __float_as_uint(fabsf((float)a[k]));
            key = (mb & 0xFFFFFFE0u) | 0x10u | (unsigned)r;  // bit4 marks "live"
        }
        unsigned best = __reduce_max_sync(hmask, key);
        int p = (int)(best & 15u);
        if (k == r) myp = p;

        double pv = __shfl_sync(FULL, a[k], p, 16);
        det *= pv;

        // Pivot lane normalizes its trailing row + rhs
        if (r == p) {
            double inv = 1.0 / pv;
#pragma unroll
            for (int c = k + 1; c < 16; c++) a[c] *= inv;
            rhs *= inv;
            elim  = true;
            sstep = k;
        }
        // Eliminate column k from all other rows (Gauss-Jordan)
        double f = a[k];
#pragma unroll
        for (int c = k + 1; c < 16; c++) {
            double pc = __shfl_sync(FULL, a[c], p, 16);
            if (r != p) a[c] -= f * pc;
        }
        double prh = __shfl_sync(FULL, rhs, p, 16);
        if (r != p) rhs -= f * prh;
    }

    // Permutation parity via inversion count of sstep sequence
    int invc = 0;
#pragma unroll
    for (int j = 0; j < 16; j++) {
        int sj = __shfl_sync(FULL, sstep, j, 16);
        if (j > r && sj < sstep) invc++;
    }
#pragma unroll
    for (int off = 8; off > 0; off >>= 1) invc += __shfl_xor_sync(FULL, invc, off, 16);
    if (invc & 1) det = -det;

    // z_i sits at the lane that pivoted at step i
    double z = __shfl_sync(FULL, rhs, myp, 16);

    out[(size_t)mat * 16 + r] = (float)(mi0 * det * z);
}

// ---------------------------------------------------------------------------
extern "C" void kernel_launch(void* const* d_in, const int* in_sizes, int n_in,
                              void* d_out, int out_size) {
    const float* X    = (const float*)d_in[0];   // eq_inputs [B][32][256]
    const float* R    = (const float*)d_in[1];   // r_ei      [B][32][8][3]
    const float* W    = (const float*)d_in[2];   // W         [2][256][16]
    const float* Bias = (const float*)d_in[3];   // b         [2][16]
    const float* ED   = (const float*)d_in[4];   // env_dim   [2][8][16][3][3]
    const float* EI   = (const float*)d_in[5];   // env_ion   [2][8][16]
    float* out = (float*)d_out;

    int B = in_sizes[0] / (32 * 256);            // 4096
    if (B > BMAX) B = BMAX;

    // Idempotent attribute set for >48KB dynamic smem (no allocation involved)
    cudaFuncSetAttribute(main_kernel,
                         cudaFuncAttributeMaxDynamicSharedMemorySize, SMEM_BYTES);

    main_kernel<<<B / 8, 256, SMEM_BYTES>>>(X, R, W, Bias, ED, EI);
    int npair = B * 2;
    cof_kernel<<<npair / 16, 256>>>(out, npair);
    (void)n_in; (void)out_size;
}

// round 7
// speedup vs baseline: 1.2334x; 1.0182x over previous
#include <cuda_runtime.h>
#include <math.h>

// Fixed shapes: B=4096, NSPIN=2, NPS=16, D=256, NION=8, DIM=3
#define BMAX 4096
typedef unsigned long long ull;

// Scratch (static device global -- no allocation)
__device__ float g_M[BMAX * 32 * 16];   // M[b][sn][o] fp32

// ---------------- f32x2 helpers (packed dual-FMA, sm_100+) ----------------
__device__ __forceinline__ ull fsplat(float a) {
    ull r; asm("mov.b64 %0, {%1, %1};" : "=l"(r) : "f"(a)); return r;
}
__device__ __forceinline__ ull fma2(ull a, ull b, ull c) {
    ull d; asm("fma.rn.f32x2 %0, %1, %2, %3;" : "=l"(d) : "l"(a), "l"(b), "l"(c)); return d;
}
__device__ __forceinline__ float pklo(ull v) { return __uint_as_float((unsigned)v); }
__device__ __forceinline__ float pkhi(ull v) { return __uint_as_float((unsigned)(v >> 32)); }

#define CP16(dst, src) \
    asm volatile("cp.async.cg.shared.global [%0], [%1], 16;" :: "r"(dst), "l"(src))

// Dynamic smem layout (floats):
//   sX: [2][256 rows][32]  XOR-swizzled  -> 16384 floats (65536 B)
//   sW: [2][256][16]                      ->  8192 floats (32768 B)
//   sG: [256][8]                          ->  2048 floats ( 8192 B)
#define SMEM_FLOATS (16384 + 8192 + 2048)
#define SMEM_BYTES  (SMEM_FLOATS * 4)     // 106496

// ---------------------------------------------------------------------------
// Kernel 1: fused  y = x@W + b  and  env = sum_i exp(-sqrt(r^T G r)) * ion,
// writes M = y*env to g_M.  (unchanged from round 5)
// ---------------------------------------------------------------------------
__global__ __launch_bounds__(256, 2) void main_kernel(
    const float* __restrict__ X,      // [B][32][256]
    const float* __restrict__ R,      // [B][32][8][3]
    const float* __restrict__ W,      // [2][256][16]
    const float* __restrict__ Bias,   // [2][16]
    const float* __restrict__ ED,     // [2][8][16][3][3]
    const float* __restrict__ EI)     // [2][8][16]
{
    extern __shared__ float smem[];
    float* sX = smem;             // swizzled X tiles
    float* sW = smem + 16384;     // full W
    float* sG = smem + 24576;     // G table

    const int tid  = threadIdx.x;
    const int blk  = blockIdx.x;
    const int rg   = tid >> 2;
    const int cg   = tid & 3;
    const int row0 = rg << 2;           // 4 rows, same spin
    const int s    = (row0 >> 4) & 1;

    const unsigned sXaddr = (unsigned)__cvta_generic_to_shared(sX);
    const unsigned sWaddr = (unsigned)__cvta_generic_to_shared(sW);

    const float* Xblk = X + (size_t)blk * 65536;

    // --- prologue: async-copy full W (8192 floats) + X chunk 0 ---
#pragma unroll
    for (int it = 0; it < 8; it++) {
        int c = it * 256 + tid;                       // 2048 16B chunks
        CP16(sWaddr + c * 16, W + c * 4);
    }
#pragma unroll
    for (int it = 0; it < 8; it++) {
        int idx = it * 256 + tid;
        int r = idx >> 3, dq = idx & 7;
        CP16(sXaddr + (r << 7) + ((dq ^ (r & 7)) << 4), Xblk + r * 256 + dq * 4);
    }
    asm volatile("cp.async.commit_group;");

    // --- G = A^T A per (s,i,o), one entry per thread (overlaps cp.async) ---
    {
        const float* A = ED + tid * 9;
        float a00=A[0],a01=A[1],a02=A[2];
        float a10=A[3],a11=A[4],a12=A[5];
        float a20=A[6],a21=A[7],a22=A[8];
        float* gp = sG + tid * 8;
        gp[0] = a00*a00 + a10*a10 + a20*a20;
        gp[1] = a01*a01 + a11*a11 + a21*a21;
        gp[2] = a02*a02 + a12*a12 + a22*a22;
        gp[3] = 2.0f*(a00*a01 + a10*a11 + a20*a21);
        gp[4] = 2.0f*(a00*a02 + a10*a12 + a20*a22);
        gp[5] = 2.0f*(a01*a02 + a11*a12 + a21*a22);
        gp[6] = EI[tid];
        gp[7] = 0.0f;
    }

    float bb[4];
#pragma unroll
    for (int j = 0; j < 4; j++) bb[j] = Bias[s * 16 + (cg << 2) + j];

    // accp[i][p]: packed (col 4cg+2p, col 4cg+2p+1) accumulators for row0+i
    ull accp[4][2];
#pragma unroll
    for (int i = 0; i < 4; i++) { accp[i][0] = 0ull; accp[i][1] = 0ull; }

#pragma unroll 1
    for (int ch = 0; ch < 8; ch++) {
        if (ch < 7) {
            const float* src   = Xblk + (ch + 1) * 32;
            unsigned     dbase = sXaddr + ((unsigned)((ch + 1) & 1)) * 32768u;
#pragma unroll
            for (int it = 0; it < 8; it++) {
                int idx = it * 256 + tid;
                int r = idx >> 3, dq = idx & 7;
                CP16(dbase + (r << 7) + ((dq ^ (r & 7)) << 4), src + r * 256 + dq * 4);
            }
            asm volatile("cp.async.commit_group;");
            asm volatile("cp.async.wait_group 1;");
        } else {
            asm volatile("cp.async.wait_group 0;");
        }
        __syncthreads();

        const float* xb = sX + (ch & 1) * 8192;
        const float* wb = sW + s * 4096 + ch * 512;   // chunk: d0 = ch*32
#pragma unroll
        for (int d4 = 0; d4 < 8; d4++) {
            float4 xq[4];
#pragma unroll
            for (int i = 0; i < 4; i++) {
                int r = row0 + i;
                xq[i] = *(const float4*)(xb + (r << 5) + ((d4 ^ (r & 7)) << 2));
            }
#pragma unroll
            for (int dd = 0; dd < 4; dd++) {
                const float* wp = wb + (d4 * 4 + dd) * 16 + (cg << 2);
                ull w01 = *(const ull*)wp;        // (w_j, w_{j+1}) contiguous pair
                ull w23 = *(const ull*)(wp + 2);
#pragma unroll
                for (int i = 0; i < 4; i++) {
                    float xv = (dd == 0) ? xq[i].x : (dd == 1) ? xq[i].y
                             : (dd == 2) ? xq[i].z : xq[i].w;
                    ull xs = fsplat(xv);
                    accp[i][0] = fma2(xs, w01, accp[i][0]);
                    accp[i][1] = fma2(xs, w23, accp[i][1]);
                }
            }
        }
        __syncthreads();
    }

    // --- Envelope + M assembly + store ---
#pragma unroll
    for (int ri = 0; ri < 4; ri++) {
        const int grow = blk * 256 + row0 + ri;     // = b*32 + sn
        const float4* rp = (const float4*)(R + (size_t)grow * 24);
        float rv[24];
#pragma unroll
        for (int q = 0; q < 6; q++) {
            float4 t = rp[q];
            rv[q*4+0] = t.x; rv[q*4+1] = t.y; rv[q*4+2] = t.z; rv[q*4+3] = t.w;
        }
        float env[4] = {0.0f, 0.0f, 0.0f, 0.0f};
#pragma unroll
        for (int i = 0; i < 8; i++) {
            float px = rv[i*3 + 0];
            float py = rv[i*3 + 1];
            float pz = rv[i*3 + 2];
#pragma unroll
            for (int cj = 0; cj < 4; cj++) {
                int gi = s * 128 + i * 16 + (cg << 2) + cj;
                float4 ga = *(const float4*)(sG + gi * 8);      // gxx,gyy,gzz,2gxy
                float4 gb = *(const float4*)(sG + gi * 8 + 4);  // 2gxz,2gyz,ion,pad
                float q1 = px * (ga.x * px + ga.w * py + gb.x * pz)
                         + py * (ga.y * py + gb.y * pz)
                         + pz * (ga.z * pz);
                float rl;
                asm("sqrt.approx.f32 %0, %1;" : "=f"(rl) : "f"(q1));
                env[cj] += __expf(-rl) * gb.z;
            }
        }
        float4 mo;
        mo.x = (pklo(accp[ri][0]) + bb[0]) * env[0];
        mo.y = (pkhi(accp[ri][0]) + bb[1]) * env[1];
        mo.z = (pklo(accp[ri][1]) + bb[2]) * env[2];
        mo.w = (pkhi(accp[ri][1]) + bb[3]) * env[3];
        *(float4*)&g_M[(size_t)grow * 16 + (cg << 2)] = mo;
    }
}

// ---------------------------------------------------------------------------
// Kernel 2: per (b,s) 16x16 matrix M, cof_i = M[i,0] * det(M) * (M^{-1})_{0,i}
// fp64 Gauss-Jordan on A = M^T, virtual partial pivoting. One matrix per
// 16-lane half-warp; rows live in registers; the pivot row is broadcast
// through a per-matrix smem buffer (STS by pivot lane, broadcast LDS by all)
// instead of fp64 shuffles -> kills the 2xSHFL latency chain.
// ---------------------------------------------------------------------------
__global__ __launch_bounds__(256) void cof_kernel(float* __restrict__ out, int npair) {
    // Per-matrix pivot buffer: [0..15]=normalized trailing row, [16]=rhs, [17]=pivot.
    // Stride 18 doubles = 144 B -> the two half-warps of a warp hit disjoint banks.
    __shared__ double pbuf[16][18];

    const unsigned FULL = 0xffffffffu;
    const int tid  = threadIdx.x;
    const int lmat = tid >> 4;                  // matrix slot within CTA (0..15)
    const int r    = tid & 15;                  // row of A (= column of M)
    const int mat  = blockIdx.x * 16 + lmat;    // (b,s) pair index
    if (mat >= npair) return;

    const unsigned hmask = 0xFFFFu << (tid & 16);  // this half-warp's lanes
    double* pb = pbuf[lmat];

    const float* Mp = g_M + (size_t)mat * 256;  // M row-major [n][o]
    double a[16];
#pragma unroll
    for (int c = 0; c < 16; c++) a[c] = (double)Mp[c * 16 + r];  // A[r][c] = M[c][r]
    double rhs = (r == 0) ? 1.0 : 0.0;
    double mi0 = (double)Mp[r * 16];            // M[r][0]

    double det = 1.0;
    int  sstep = 16;     // step at which this lane was pivot
    int  myp   = 0;      // pivot lane chosen at step k == r
    bool elim  = false;

#pragma unroll
    for (int k = 0; k < 16; k++) {
        // --- pivot: argmax |a[k]| among non-eliminated lanes (1 redux) ---
        unsigned key = 0u;
        if (!elim) {
            unsigned mb = __float_as_uint(fabsf((float)a[k]));
            key = (mb & 0xFFFFFFE0u) | 0x10u | (unsigned)r;  // bit4 marks "live"
        }
        unsigned best = __reduce_max_sync(hmask, key);
        int p = (int)(best & 15u);
        if (k == r) myp = p;
        bool ispiv = (r == p);

        // Pivot lane publishes pivot value + normalized trailing row + rhs
        if (ispiv) {
            double pv  = a[k];
            double inv = 1.0 / pv;
            pb[17] = pv;
#pragma unroll
            for (int c = k + 1; c < 16; c++) { a[c] *= inv; pb[c] = a[c]; }
            rhs *= inv;
            pb[16] = rhs;
            elim  = true;
            sstep = k;
        }
        __syncwarp(FULL);

        det *= pb[17];

        // Non-pivot lanes eliminate column k using the broadcast pivot row
        if (!ispiv) {
            double f = a[k];
#pragma unroll
            for (int c = k + 1; c < 16; c++) a[c] -= f * pb[c];
            rhs -= f * pb[16];
        }
        __syncwarp(FULL);   // protect pbuf before next step's pivot overwrites it
    }

    // Permutation parity via inversion count of sstep sequence (int shuffles)
    int invc = 0;
#pragma unroll
    for (int j = 0; j < 16; j++) {
        int sj = __shfl_sync(FULL, sstep, j, 16);
        if (j > r && sj < sstep) invc++;
    }
#pragma unroll
    for (int off = 8; off > 0; off >>= 1) invc += __shfl_xor_sync(FULL, invc, off, 16);
    if (invc & 1) det = -det;

    // z_i sits at the lane that pivoted at step i
    double z = __shfl_sync(FULL, rhs, myp, 16);

    out[(size_t)mat * 16 + r] = (float)(mi0 * det * z);
}

// ---------------------------------------------------------------------------
extern "C" void kernel_launch(void* const* d_in, const int* in_sizes, int n_in,
                              void* d_out, int out_size) {
    const float* X    = (const float*)d_in[0];   // eq_inputs [B][32][256]
    const float* R    = (const float*)d_in[1];   // r_ei      [B][32][8][3]
    const float* W    = (const float*)d_in[2];   // W         [2][256][16]
    const float* Bias = (const float*)d_in[3];   // b         [2][16]
    const float* ED   = (const float*)d_in[4];   // env_dim   [2][8][16][3][3]
    const float* EI   = (const float*)d_in[5];   // env_ion   [2][8][16]
    float* out = (float*)d_out;

    int B = in_sizes[0] / (32 * 256);            // 4096
    if (B > BMAX) B = BMAX;

    // Idempotent attribute set for >48KB dynamic smem (no allocation involved)
    cudaFuncSetAttribute(main_kernel,
                         cudaFuncAttributeMaxDynamicSharedMemorySize, SMEM_BYTES);

    main_kernel<<<B / 8, 256, SMEM_BYTES>>>(X, R, W, Bias, ED, EI);
    int npair = B * 2;
    cof_kernel<<<(npair + 15) / 16, 256>>>(out, npair);
    (void)n_in; (void)out_size;
}

// round 8
// speedup vs baseline: 2.4166x; 1.9593x over previous
#include <cuda_runtime.h>
#include <math.h>

// Fixed shapes: B=4096, NSPIN=2, NPS=16, D=256, NION=8, DIM=3
#define BMAX 4096
typedef unsigned long long ull;

// Scratch (static device global -- no allocation)
__device__ float g_M[BMAX * 32 * 16];   // M[b][sn][o] fp32

// ---------------- f32x2 helpers (packed dual-FMA, sm_100+) ----------------
__device__ __forceinline__ ull fsplat(float a) {
    ull r; asm("mov.b64 %0, {%1, %1};" : "=l"(r) : "f"(a)); return r;
}
__device__ __forceinline__ ull fma2(ull a, ull b, ull c) {
    ull d; asm("fma.rn.f32x2 %0, %1, %2, %3;" : "=l"(d) : "l"(a), "l"(b), "l"(c)); return d;
}
__device__ __forceinline__ float pklo(ull v) { return __uint_as_float((unsigned)v); }
__device__ __forceinline__ float pkhi(ull v) { return __uint_as_float((unsigned)(v >> 32)); }

#define CP16(dst, src) \
    asm volatile("cp.async.cg.shared.global [%0], [%1], 16;" :: "r"(dst), "l"(src))

// Dynamic smem layout (floats):
//   sX: [2][256 rows][32]  XOR-swizzled  -> 16384 floats (65536 B)
//   sW: [2][256][16]                      ->  8192 floats (32768 B)
//   sG: [256][8]                          ->  2048 floats ( 8192 B)
#define SMEM_FLOATS (16384 + 8192 + 2048)
#define SMEM_BYTES  (SMEM_FLOATS * 4)     // 106496

// ---------------------------------------------------------------------------
// Kernel 1: fused  y = x@W + b  and  env = sum_i exp(-sqrt(r^T G r)) * ion,
// writes M = y*env to g_M.  (unchanged -- isolating the cof change)
// ---------------------------------------------------------------------------
__global__ __launch_bounds__(256, 2) void main_kernel(
    const float* __restrict__ X,      // [B][32][256]
    const float* __restrict__ R,      // [B][32][8][3]
    const float* __restrict__ W,      // [2][256][16]
    const float* __restrict__ Bias,   // [2][16]
    const float* __restrict__ ED,     // [2][8][16][3][3]
    const float* __restrict__ EI)     // [2][8][16]
{
    extern __shared__ float smem[];
    float* sX = smem;             // swizzled X tiles
    float* sW = smem + 16384;     // full W
    float* sG = smem + 24576;     // G table

    const int tid  = threadIdx.x;
    const int blk  = blockIdx.x;
    const int rg   = tid >> 2;
    const int cg   = tid & 3;
    const int row0 = rg << 2;           // 4 rows, same spin
    const int s    = (row0 >> 4) & 1;

    const unsigned sXaddr = (unsigned)__cvta_generic_to_shared(sX);
    const unsigned sWaddr = (unsigned)__cvta_generic_to_shared(sW);

    const float* Xblk = X + (size_t)blk * 65536;

    // --- prologue: async-copy full W (8192 floats) + X chunk 0 ---
#pragma unroll
    for (int it = 0; it < 8; it++) {
        int c = it * 256 + tid;                       // 2048 16B chunks
        CP16(sWaddr + c * 16, W + c * 4);
    }
#pragma unroll
    for (int it = 0; it < 8; it++) {
        int idx = it * 256 + tid;
        int r = idx >> 3, dq = idx & 7;
        CP16(sXaddr + (r << 7) + ((dq ^ (r & 7)) << 4), Xblk + r * 256 + dq * 4);
    }
    asm volatile("cp.async.commit_group;");

    // --- G = A^T A per (s,i,o), one entry per thread (overlaps cp.async) ---
    {
        const float* A = ED + tid * 9;
        float a00=A[0],a01=A[1],a02=A[2];
        float a10=A[3],a11=A[4],a12=A[5];
        float a20=A[6],a21=A[7],a22=A[8];
        float* gp = sG + tid * 8;
        gp[0] = a00*a00 + a10*a10 + a20*a20;
        gp[1] = a01*a01 + a11*a11 + a21*a21;
        gp[2] = a02*a02 + a12*a12 + a22*a22;
        gp[3] = 2.0f*(a00*a01 + a10*a11 + a20*a21);
        gp[4] = 2.0f*(a00*a02 + a10*a12 + a20*a22);
        gp[5] = 2.0f*(a01*a02 + a11*a12 + a21*a22);
        gp[6] = EI[tid];
        gp[7] = 0.0f;
    }

    float bb[4];
#pragma unroll
    for (int j = 0; j < 4; j++) bb[j] = Bias[s * 16 + (cg << 2) + j];

    // accp[i][p]: packed (col 4cg+2p, col 4cg+2p+1) accumulators for row0+i
    ull accp[4][2];
#pragma unroll
    for (int i = 0; i < 4; i++) { accp[i][0] = 0ull; accp[i][1] = 0ull; }

#pragma unroll 1
    for (int ch = 0; ch < 8; ch++) {
        if (ch < 7) {
            const float* src   = Xblk + (ch + 1) * 32;
            unsigned     dbase = sXaddr + ((unsigned)((ch + 1) & 1)) * 32768u;
#pragma unroll
            for (int it = 0; it < 8; it++) {
                int idx = it * 256 + tid;
                int r = idx >> 3, dq = idx & 7;
                CP16(dbase + (r << 7) + ((dq ^ (r & 7)) << 4), src + r * 256 + dq * 4);
            }
            asm volatile("cp.async.commit_group;");
            asm volatile("cp.async.wait_group 1;");
        } else {
            asm volatile("cp.async.wait_group 0;");
        }
        __syncthreads();

        const float* xb = sX + (ch & 1) * 8192;
        const float* wb = sW + s * 4096 + ch * 512;   // chunk: d0 = ch*32
#pragma unroll
        for (int d4 = 0; d4 < 8; d4++) {
            float4 xq[4];
#pragma unroll
            for (int i = 0; i < 4; i++) {
                int r = row0 + i;
                xq[i] = *(const float4*)(xb + (r << 5) + ((d4 ^ (r & 7)) << 2));
            }
#pragma unroll
            for (int dd = 0; dd < 4; dd++) {
                const float* wp = wb + (d4 * 4 + dd) * 16 + (cg << 2);
                ull w01 = *(const ull*)wp;        // (w_j, w_{j+1}) contiguous pair
                ull w23 = *(const ull*)(wp + 2);
#pragma unroll
                for (int i = 0; i < 4; i++) {
                    float xv = (dd == 0) ? xq[i].x : (dd == 1) ? xq[i].y
                             : (dd == 2) ? xq[i].z : xq[i].w;
                    ull xs = fsplat(xv);
                    accp[i][0] = fma2(xs, w01, accp[i][0]);
                    accp[i][1] = fma2(xs, w23, accp[i][1]);
                }
            }
        }
        __syncthreads();
    }

    // --- Envelope + M assembly + store ---
#pragma unroll
    for (int ri = 0; ri < 4; ri++) {
        const int grow = blk * 256 + row0 + ri;     // = b*32 + sn
        const float4* rp = (const float4*)(R + (size_t)grow * 24);
        float rv[24];
#pragma unroll
        for (int q = 0; q < 6; q++) {
            float4 t = rp[q];
            rv[q*4+0] = t.x; rv[q*4+1] = t.y; rv[q*4+2] = t.z; rv[q*4+3] = t.w;
        }
        float env[4] = {0.0f, 0.0f, 0.0f, 0.0f};
#pragma unroll
        for (int i = 0; i < 8; i++) {
            float px = rv[i*3 + 0];
            float py = rv[i*3 + 1];
            float pz = rv[i*3 + 2];
#pragma unroll
            for (int cj = 0; cj < 4; cj++) {
                int gi = s * 128 + i * 16 + (cg << 2) + cj;
                float4 ga = *(const float4*)(sG + gi * 8);      // gxx,gyy,gzz,2gxy
                float4 gb = *(const float4*)(sG + gi * 8 + 4);  // 2gxz,2gyz,ion,pad
                float q1 = px * (ga.x * px + ga.w * py + gb.x * pz)
                         + py * (ga.y * py + gb.y * pz)
                         + pz * (ga.z * pz);
                float rl;
                asm("sqrt.approx.f32 %0, %1;" : "=f"(rl) : "f"(q1));
                env[cj] += __expf(-rl) * gb.z;
            }
        }
        float4 mo;
        mo.x = (pklo(accp[ri][0]) + bb[0]) * env[0];
        mo.y = (pkhi(accp[ri][0]) + bb[1]) * env[1];
        mo.z = (pklo(accp[ri][1]) + bb[2]) * env[2];
        mo.w = (pkhi(accp[ri][1]) + bb[3]) * env[3];
        *(float4*)&g_M[(size_t)grow * 16 + (cg << 2)] = mo;
    }
}

// ---------------------------------------------------------------------------
// Kernel 2: per (b,s) 16x16 matrix M, cof_i = M[i,0] * det(M) * (M^{-1})_{0,i}
// FP32 Gauss-Jordan on A = M^T with virtual partial pivoting (same numerics
// class as the reference's fp32 jnp.linalg.det LU). One matrix per 16-lane
// half-warp; rows in registers; pivot row broadcast via per-matrix smem slot.
// fp64 eliminated entirely -- B300's fp64 pipe (rt ~18.4 cyc/SM) was the
// bottleneck.
// ---------------------------------------------------------------------------
__global__ __launch_bounds__(256) void cof_kernel(float* __restrict__ out, int npair) {
    // Per-matrix pivot buffer: [0..15]=normalized trailing row, [16]=rhs, [17]=pivot.
    __shared__ float pbuf[16][18];

    const unsigned FULL = 0xffffffffu;
    const int tid  = threadIdx.x;
    const int lmat = tid >> 4;                  // matrix slot within CTA (0..15)
    const int r    = tid & 15;                  // row of A (= column of M)
    const int mat  = blockIdx.x * 16 + lmat;    // (b,s) pair index
    if (mat >= npair) return;

    const unsigned hmask = 0xFFFFu << (tid & 16);  // this half-warp's lanes
    float* pb = pbuf[lmat];

    const float* Mp = g_M + (size_t)mat * 256;  // M row-major [n][o]
    float a[16];
#pragma unroll
    for (int c = 0; c < 16; c++) a[c] = Mp[c * 16 + r];   // A[r][c] = M[c][r]
    float rhs = (r == 0) ? 1.0f : 0.0f;
    float mi0 = Mp[r * 16];                     // M[r][0]

    float det = 1.0f;
    int  sstep = 16;     // step at which this lane was pivot
    int  myp   = 0;      // pivot lane chosen at step k == r
    bool elim  = false;

#pragma unroll
    for (int k = 0; k < 16; k++) {
        // --- pivot: argmax |a[k]| among non-eliminated lanes (1 redux) ---
        unsigned key = 0u;
        if (!elim) {
            unsigned mb = __float_as_uint(fabsf(a[k]));
            key = (mb & 0xFFFFFFE0u) | 0x10u | (unsigned)r;  // bit4 marks "live"
        }
        unsigned best = __reduce_max_sync(hmask, key);
        int p = (int)(best & 15u);
        if (k == r) myp = p;
        bool ispiv = (r == p);

        // Pivot lane publishes pivot value + normalized trailing row + rhs
        if (ispiv) {
            float pv  = a[k];
            float inv = 1.0f / pv;
            pb[17] = pv;
#pragma unroll
            for (int c = k + 1; c < 16; c++) { a[c] *= inv; pb[c] = a[c]; }
            rhs *= inv;
            pb[16] = rhs;
            elim  = true;
            sstep = k;
        }
        __syncwarp(FULL);

        det *= pb[17];

        // Non-pivot lanes eliminate column k using the broadcast pivot row
        if (!ispiv) {
            float f = a[k];
#pragma unroll
            for (int c = k + 1; c < 16; c++) a[c] = fmaf(-f, pb[c], a[c]);
            rhs = fmaf(-f, pb[16], rhs);
        }
        __syncwarp(FULL);   // protect pbuf before next step's pivot overwrites it
    }

    // Permutation parity via inversion count of sstep sequence (int shuffles)
    int invc = 0;
#pragma unroll
    for (int j = 0; j < 16; j++) {
        int sj = __shfl_sync(FULL, sstep, j, 16);
        if (j > r && sj < sstep) invc++;
    }
#pragma unroll
    for (int off = 8; off > 0; off >>= 1) invc += __shfl_xor_sync(FULL, invc, off, 16);
    if (invc & 1) det = -det;

    // z_i sits at the lane that pivoted at step i
    float z = __shfl_sync(FULL, rhs, myp, 16);

    out[(size_t)mat * 16 + r] = mi0 * det * z;
}

// ---------------------------------------------------------------------------
extern "C" void kernel_launch(void* const* d_in, const int* in_sizes, int n_in,
                              void* d_out, int out_size) {
    const float* X    = (const float*)d_in[0];   // eq_inputs [B][32][256]
    const float* R    = (const float*)d_in[1];   // r_ei      [B][32][8][3]
    const float* W    = (const float*)d_in[2];   // W         [2][256][16]
    const float* Bias = (const float*)d_in[3];   // b         [2][16]
    const float* ED   = (const float*)d_in[4];   // env_dim   [2][8][16][3][3]
    const float* EI   = (const float*)d_in[5];   // env_ion   [2][8][16]
    float* out = (float*)d_out;

    int B = in_sizes[0] / (32 * 256);            // 4096
    if (B > BMAX) B = BMAX;

    // Idempotent attribute set for >48KB dynamic smem (no allocation involved)
    cudaFuncSetAttribute(main_kernel,
                         cudaFuncAttributeMaxDynamicSharedMemorySize, SMEM_BYTES);

    main_kernel<<<B / 8, 256, SMEM_BYTES>>>(X, R, W, Bias, ED, EI);
    int npair = B * 2;
    cof_kernel<<<(npair + 15) / 16, 256>>>(out, npair);
    (void)n_in; (void)out_size;
}